// round 10
// baseline (speedup 1.0000x reference)
#include <cuda_runtime.h>
#include <cstdint>

// QuantizedLinear: y[b,o] = scale[o] * sum_k x[b,k]*W[o,k] + bias[o]
//   x: f32 [16,4096], W: int32 [11008,4096] (int8-range), scale/bias f32,
//   out f32 [16,11008].
//
// R8 redesign (fixing L1tex wavefront bound of R5):
//   - acc pairs by K-parity, not batch: acc[c][b] = f32x2 {sum even k, sum odd k}.
//     => x operand for fma.rn.f32x2 is the NATIVE x row layout (16B/lane,
//     contiguous), and weight pairs come straight from int4 conversion.
//     No pack kernel, no operand-duplication MOVs.
//   - x is staged in 32KB smem chunks (512 k each, 8 chunks) and read via
//     LDS.128 (conflict-free: 16B lane stride => each 8-lane phase hits all
//     32 banks once). x traffic (704MB) moves off the L1tex wavefront queue
//     onto the smem crossbar (128 B/cyc/SM).
//   - Weights stream once via __ldcs (evict-first), fully coalesced.
//   - Single kernel over full K (smem removes the L1-residency constraint),
//     so one launch, bias folded in, no out read-modify-write.

#define IN_F    4096
#define OUT_F   11008
#define BATCH   16
#define CH      4                       // output channels per warp
#define WARPS_PER_CTA 4
#define THREADS (WARPS_PER_CTA * 32)    // 128
#define KV_ROW  (IN_F / 4)              // 1024 int4 (or float4) per row
#define CHUNK_KV 128                    // float4 units per chunk = 512 floats
#define NCHUNK  (KV_ROW / CHUNK_KV)     // 8
#define ITERS_PER_CHUNK (CHUNK_KV / 32) // 4

__device__ __forceinline__ unsigned long long pack2(float lo, float hi) {
    unsigned long long r;
    asm("mov.b64 %0, {%1, %2};" : "=l"(r) : "f"(lo), "f"(hi));
    return r;
}

__device__ __forceinline__ void fma2(unsigned long long& acc,
                                     unsigned long long a,
                                     unsigned long long b) {
    asm("fma.rn.f32x2 %0, %1, %2, %0;" : "+l"(acc) : "l"(a), "l"(b));
}

__global__ void __launch_bounds__(THREADS, 2)
qlin_kernel(const float4* __restrict__ X,     // x viewed as [16][1024] float4
            const int4*   __restrict__ Wv,    // W viewed as [11008][1024] int4
            const float*  __restrict__ scale,
            const float*  __restrict__ bias,
            float*        __restrict__ out)
{
    __shared__ float4 xs[BATCH * CHUNK_KV];   // 32 KB: [b][kvl]

    const int tid  = threadIdx.x;
    const int lane = tid & 31;
    const int warp = tid >> 5;
    const int o0   = (blockIdx.x * WARPS_PER_CTA + warp) * CH;

    // acc[c][b]: f32x2 pair = {partial sum over even k, over odd k}
    unsigned long long acc[CH][BATCH];
#pragma unroll
    for (int c = 0; c < CH; ++c)
#pragma unroll
        for (int b = 0; b < BATCH; ++b) acc[c][b] = 0ull;

#pragma unroll 1
    for (int chunk = 0; chunk < NCHUNK; ++chunk) {
        __syncthreads();   // previous chunk's reads done before overwrite
        // Stage x chunk: 2048 float4 by 128 threads (16 each), coalesced.
#pragma unroll
        for (int i = 0; i < (BATCH * CHUNK_KV) / THREADS; ++i) {
            const int idx = i * THREADS + tid;        // = b*CHUNK_KV + kvl
            const int b   = idx / CHUNK_KV;
            const int kvl = idx % CHUNK_KV;
            xs[idx] = X[b * KV_ROW + chunk * CHUNK_KV + kvl];
        }
        __syncthreads();

#pragma unroll
        for (int it = 0; it < ITERS_PER_CHUNK; ++it) {
            const int kvl = it * 32 + lane;             // 0..127
            const int kv  = chunk * CHUNK_KV + kvl;     // 0..1023

            // 4 channels' weights for k = 4kv..4kv+3 (streaming, coalesced)
            int4 wi[CH];
#pragma unroll
            for (int c = 0; c < CH; ++c)
                wi[c] = __ldcs(&Wv[(o0 + c) * KV_ROW + kv]);

            // Natural k-pairs: {w[4kv],w[4kv+1]} and {w[4kv+2],w[4kv+3]}
            unsigned long long wp[CH][2];
#pragma unroll
            for (int c = 0; c < CH; ++c) {
                wp[c][0] = pack2((float)wi[c].x, (float)wi[c].y);
                wp[c][1] = pack2((float)wi[c].z, (float)wi[c].w);
            }

#pragma unroll
            for (int b = 0; b < BATCH; ++b) {
                // x[b][4kv..4kv+3]: 16B contiguous, conflict-free LDS.128
                const ulonglong2 xv = *reinterpret_cast<const ulonglong2*>(
                    &xs[b * CHUNK_KV + kvl]);
#pragma unroll
                for (int c = 0; c < CH; ++c) {
                    fma2(acc[c][b], wp[c][0], xv.x);
                    fma2(acc[c][b], wp[c][1], xv.y);
                }
            }
        }
    }

    // Epilogue: fold k-parity halves, warp-reduce over lanes (k-strided),
    // scale + bias, write.
#pragma unroll
    for (int c = 0; c < CH; ++c) {
        const int   o  = o0 + c;
        const float sc = scale[o];
        const float bi = bias[o];
#pragma unroll
        for (int b = 0; b < BATCH; ++b) {
            float lo, hi;
            asm("mov.b64 {%0, %1}, %2;" : "=f"(lo), "=f"(hi) : "l"(acc[c][b]));
            float s = lo + hi;
#pragma unroll
            for (int off = 16; off > 0; off >>= 1)
                s += __shfl_xor_sync(0xffffffffu, s, off);
            if (lane == 0) out[b * OUT_F + o] = s * sc + bi;
        }
    }
}

extern "C" void kernel_launch(void* const* d_in, const int* in_sizes, int n_in,
                              void* d_out, int out_size) {
    // metadata order: x (f32), weight_int8 (int32), weight_scale (f32), bias (f32)
    const float4* X     = (const float4*)d_in[0];
    const int4*   Wv    = (const int4*)d_in[1];
    const float*  scale = (const float*)d_in[2];
    const float*  bias  = (const float*)d_in[3];
    float*        out   = (float*)d_out;
    (void)in_sizes; (void)n_in; (void)out_size;

    const int blocks = OUT_F / (WARPS_PER_CTA * CH);   // 688
    qlin_kernel<<<blocks, THREADS>>>(X, Wv, scale, bias, out);
}

// round 11
// speedup vs baseline: 1.1000x; 1.1000x over previous
#include <cuda_runtime.h>
#include <cstdint>

// QuantizedLinear: y[b,o] = scale[o] * sum_k x[b,k]*W[o,k] + bias[o]
//   x: f32 [16,4096], W: int32 [11008,4096] (int8-range), scale/bias f32,
//   out f32 [16,11008].
//
// R10: occupancy fix. R8 burned 128 regs on k-parity f32x2 accumulators
// (250 regs -> 2 CTAs/SM, issue 27%). Now:
//   - acc paired over BATCH: acc[c][p] = f32x2 {out(2p), out(2p+1)} = 64 regs.
//   - x staged into smem already batch-pair-packed and lane-swizzled:
//     per (it,p) a 512B block A[32 lanes]x16B then B[32]x16B, so inner-loop
//     LDS.128 has 16B lane stride => conflict-free.
//   - weight operand = dup{w,w} via mov.b64 (alu pipe), int4 loads via __ldcs.
//   - software prefetch of next iter's weights (crosses chunk barriers).
//   - __launch_bounds__(128,3): 12 warps/SM, smem 3x32KB = 96KB.

#define IN_F     4096
#define OUT_F    11008
#define BATCH    16
#define NPAIR    8                     // batch pairs
#define CH       4                     // output channels per warp
#define WARPS    4
#define THREADS  (WARPS * 32)          // 128
#define KV_ROW   (IN_F / 4)            // 1024 int4/float4 per row
#define CHUNK_KV 128                   // k-quads per chunk = 512 k
#define NCHUNK   (KV_ROW / CHUNK_KV)   // 8
#define ITERS    (CHUNK_KV / 32)       // 4 iters per chunk
#define GITERS   (NCHUNK * ITERS)      // 32 total k-iters

__device__ __forceinline__ unsigned long long dup_f32(float a) {
    unsigned long long r;
    asm("mov.b64 %0, {%1, %1};" : "=l"(r) : "f"(a));
    return r;
}

__device__ __forceinline__ void fma2(unsigned long long& acc,
                                     unsigned long long a,
                                     unsigned long long b) {
    asm("fma.rn.f32x2 %0, %1, %2, %0;" : "+l"(acc) : "l"(a), "l"(b));
}

__global__ void __launch_bounds__(THREADS, 3)
qlin_kernel(const float4* __restrict__ X,     // x as [16][1024] float4
            const int4*   __restrict__ Wv,    // W as [11008][1024] int4
            const float*  __restrict__ scale,
            const float*  __restrict__ bias,
            float*        __restrict__ out)
{
    // Swizzled pair-packed x chunk, 32 KB:
    // float4 xs[it(4)][p(8)][ab(2)][lane(32)]
    //   A[lane] = {x[2p][k0], x[2p+1][k0], x[2p][k1], x[2p+1][k1]}
    //   B[lane] = {x[2p][k2], x[2p+1][k2], x[2p][k3], x[2p+1][k3]}
    // with k0..k3 = 4*(chunk*128 + it*32 + lane) ..+3
    __shared__ float4 xs[ITERS * NPAIR * 2 * 32];

    const int tid  = threadIdx.x;
    const int lane = tid & 31;
    const int warp = tid >> 5;
    const int o0   = (blockIdx.x * WARPS + warp) * CH;

    unsigned long long acc[CH][NPAIR];
#pragma unroll
    for (int c = 0; c < CH; ++c)
#pragma unroll
        for (int p = 0; p < NPAIR; ++p) acc[c][p] = 0ull;

    const int wrow = o0 * KV_ROW;      // int4 index of channel o0's row

    // Prefetch weights for global iter 0.
    int4 wn[CH];
#pragma unroll
    for (int c = 0; c < CH; ++c)
        wn[c] = __ldcs(&Wv[wrow + c * KV_ROW + lane]);

#pragma unroll 1
    for (int chunk = 0; chunk < NCHUNK; ++chunk) {
        __syncthreads();   // prior chunk's reads complete before overwrite

        // Stage: 1024 (p,kvl) items, 8 per thread; i == p, kvl == tid.
#pragma unroll
        for (int p = 0; p < NPAIR; ++p) {
            const float4 r0 = X[(2 * p)     * KV_ROW + chunk * CHUNK_KV + tid];
            const float4 r1 = X[(2 * p + 1) * KV_ROW + chunk * CHUNK_KV + tid];
            const int it = tid >> 5;
            const int ln = tid & 31;
            float4 A, B;
            A.x = r0.x; A.y = r1.x; A.z = r0.y; A.w = r1.y;
            B.x = r0.z; B.y = r1.z; B.z = r0.w; B.w = r1.w;
            xs[((it * NPAIR + p) * 2 + 0) * 32 + ln] = A;
            xs[((it * NPAIR + p) * 2 + 1) * 32 + ln] = B;
        }
        __syncthreads();

#pragma unroll
        for (int it = 0; it < ITERS; ++it) {
            // Consume prefetched weights; start next iter's loads.
            int4 wi[CH];
#pragma unroll
            for (int c = 0; c < CH; ++c) wi[c] = wn[c];

            const int gn = chunk * ITERS + it + 1;
            if (gn < GITERS) {
#pragma unroll
                for (int c = 0; c < CH; ++c)
                    wn[c] = __ldcs(&Wv[wrow + c * KV_ROW + gn * 32 + lane]);
            }

            // Duplicate each weight into both f32x2 halves.
            unsigned long long w0[CH], w1[CH], w2[CH], w3[CH];
#pragma unroll
            for (int c = 0; c < CH; ++c) {
                w0[c] = dup_f32((float)wi[c].x);
                w1[c] = dup_f32((float)wi[c].y);
                w2[c] = dup_f32((float)wi[c].z);
                w3[c] = dup_f32((float)wi[c].w);
            }

#pragma unroll
            for (int p = 0; p < NPAIR; ++p) {
                const ulonglong2 A = *reinterpret_cast<const ulonglong2*>(
                    &xs[((it * NPAIR + p) * 2 + 0) * 32 + lane]);
                const ulonglong2 B = *reinterpret_cast<const ulonglong2*>(
                    &xs[((it * NPAIR + p) * 2 + 1) * 32 + lane]);
#pragma unroll
                for (int c = 0; c < CH; ++c) {
                    fma2(acc[c][p], w0[c], A.x);   // k0, batches {2p,2p+1}
                    fma2(acc[c][p], w1[c], A.y);   // k1
                    fma2(acc[c][p], w2[c], B.x);   // k2
                    fma2(acc[c][p], w3[c], B.y);   // k3
                }
            }
        }
    }

    // Epilogue: each acc half is one output's lane-partial. Reduce, scale+bias.
#pragma unroll
    for (int c = 0; c < CH; ++c) {
        const int   o  = o0 + c;
        const float sc = scale[o];
        const float bi = bias[o];
#pragma unroll
        for (int p = 0; p < NPAIR; ++p) {
            float lo, hi;
            asm("mov.b64 {%0, %1}, %2;" : "=f"(lo), "=f"(hi) : "l"(acc[c][p]));
#pragma unroll
            for (int off = 16; off > 0; off >>= 1) {
                lo += __shfl_xor_sync(0xffffffffu, lo, off);
                hi += __shfl_xor_sync(0xffffffffu, hi, off);
            }
            if (lane == 0) {
                out[(2 * p)     * OUT_F + o] = lo * sc + bi;
                out[(2 * p + 1) * OUT_F + o] = hi * sc + bi;
            }
        }
    }
}

extern "C" void kernel_launch(void* const* d_in, const int* in_sizes, int n_in,
                              void* d_out, int out_size) {
    // metadata order: x (f32), weight_int8 (int32), weight_scale (f32), bias (f32)
    const float4* X     = (const float4*)d_in[0];
    const int4*   Wv    = (const int4*)d_in[1];
    const float*  scale = (const float*)d_in[2];
    const float*  bias  = (const float*)d_in[3];
    float*        out   = (float*)d_out;
    (void)in_sizes; (void)n_in; (void)out_size;

    const int blocks = OUT_F / (WARPS * CH);   // 688
    qlin_kernel<<<blocks, THREADS>>>(X, Wv, scale, bias, out);
}